// round 10
// baseline (speedup 1.0000x reference)
#include <cuda_runtime.h>
#include <cstdint>

#define NBINS 64
#define ROW_LEN 8192
#define BLOCK_THREADS 256
#define ROWS_PER_BLOCK 4
#define CHUNK_FLOATS 1024                       // 4 KB per chunk
#define CHUNK_BYTES (CHUNK_FLOATS * 4)
#define CHUNKS_PER_ROW (ROW_LEN / CHUNK_FLOATS) // 8
#define NCHUNKS (ROWS_PER_BLOCK * CHUNKS_PER_ROW) // 32
#define NBUF 3

// Data path: TMA bulk (cp.async.bulk, UBLKCP) GMEM->SMEM ring, consumed via
// LDS — bypasses the per-warp L1TEX wavefront queue that caused the
// cross-CTA finish-time spread. Counters keep the proven R7 layout:
// priv[slab][bin][32] u32, low/high u16 half = row (2g)/(2g+1); bank = lane,
// every atomic conflict-free, increment a per-chunk constant.
// Max count per half-word: 256 elems per (row, lane-column) << 65536.
// smem ~28.7 KB/block -> 7 blocks/SM -> grid 1024 <= 1036: single wave.
struct __align__(128) Smem {
    unsigned int priv[2][NBINS][32];            // 16 KB counters
    float4 stage[NBUF][CHUNK_FLOATS / 4];       // 12 KB staging ring
    unsigned long long mbar[NBUF];
};

__device__ __forceinline__ uint32_t s2u(const void* p) {
    return (uint32_t)__cvta_generic_to_shared(p);
}

__device__ __forceinline__ void tma_issue(uint32_t dst, const float* src,
                                          uint32_t mbar) {
    asm volatile(
        "mbarrier.arrive.expect_tx.shared::cta.b64 _, [%0], %1;"
        :: "r"(mbar), "r"((unsigned)CHUNK_BYTES) : "memory");
    asm volatile(
        "cp.async.bulk.shared::cta.global.mbarrier::complete_tx::bytes "
        "[%0], [%1], %2, [%3];"
        :: "r"(dst), "l"(src), "r"((unsigned)CHUNK_BYTES), "r"(mbar)
        : "memory");
}

__device__ __forceinline__ void mbar_wait(uint32_t mbar, unsigned phase) {
    unsigned done;
    asm volatile(
        "{\n\t.reg .pred p;\n\t"
        "mbarrier.try_wait.parity.acquire.cta.shared::cta.b64 p, [%1], %2;\n\t"
        "selp.b32 %0, 1, 0, p;\n\t}"
        : "=r"(done) : "r"(mbar), "r"(phase) : "memory");
    while (!done) {
        asm volatile(
            "{\n\t.reg .pred p;\n\t"
            "mbarrier.try_wait.parity.acquire.cta.shared::cta.b64 p, [%1], %2, 0x989680;\n\t"
            "selp.b32 %0, 1, 0, p;\n\t}"
            : "=r"(done) : "r"(mbar), "r"(phase) : "memory");
    }
}

__global__ __launch_bounds__(BLOCK_THREADS, 7)
void hist_rows_kernel(const float* __restrict__ x, float* __restrict__ out) {
    __shared__ Smem s;
    const int tid  = threadIdx.x;
    const int lane = tid & 31;

    // Zero counters (4096 words / 256 threads = 16 each).
    unsigned int* flat = &s.priv[0][0][0];
    #pragma unroll
    for (int i = 0; i < (2 * NBINS * 32) / BLOCK_THREADS; i++)
        flat[tid + i * BLOCK_THREADS] = 0u;

    if (tid == 0) {
        #pragma unroll
        for (int b = 0; b < NBUF; b++)
            asm volatile("mbarrier.init.shared.b64 [%0], %1;"
                         :: "r"(s2u(&s.mbar[b])), "r"(1) : "memory");
    }
    __syncthreads();   // counters zeroed + mbars initialized for everyone

    const float* base = x + (size_t)blockIdx.x * ROWS_PER_BLOCK * ROW_LEN;

    // Prologue: fill the ring.
    if (tid == 0) {
        #pragma unroll
        for (int c = 0; c < NBUF; c++)
            tma_issue(s2u(&s.stage[c][0]), base + c * CHUNK_FLOATS,
                      s2u(&s.mbar[c]));
    }

    const float scale = 64.0f / 6.0f;   // NBINS/(VMAX-VMIN), fp32-rounded like ref
    unsigned int* cell0 = &s.priv[0][0][0] + lane;

    #pragma unroll 1
    for (int c = 0; c < NCHUNKS; c++) {
        const int buf = c % NBUF;
        mbar_wait(s2u(&s.mbar[buf]), (unsigned)((c / NBUF) & 1));

        float4 v = s.stage[buf][tid];   // LDS.128, lane-contiguous

        const int r = c / CHUNKS_PER_ROW;             // local row of this chunk
        unsigned int* cell = cell0 + (r >> 1) * (NBINS * 32);
        const unsigned int incr = (r & 1) ? 0x10000u : 1u;

        float f[4] = {v.x, v.y, v.z, v.w};
        #pragma unroll
        for (int j = 0; j < 4; j++) {
            // Exactly the reference fp32 sequence: (x - VMIN), * scale,
            // floor (round toward -inf), clamp to [0, 63].
            int b = __float2int_rd(__fmul_rn(__fadd_rn(f[j], 3.0f), scale));
            b = max(0, min(NBINS - 1, b));
            atomicAdd(&cell[b * 32], incr);           // bank = lane, 1 wavefront
        }

        __syncthreads();   // all consumed buf -> safe to refill it
        if (tid == 0 && c + NBUF < NCHUNKS)
            tma_issue(s2u(&s.stage[buf][0]),
                      base + (c + NBUF) * CHUNK_FLOATS, s2u(&s.mbar[buf]));
    }

    // Last loop iteration ended with __syncthreads(): counters final.

    // Reduce: 256 outputs per block = 1 per thread. row = tid>>6, bin = tid&63.
    // Rotated column (t+lane)&31 keeps banks distinct per lane.
    const int r = tid >> 6;
    const int bin = tid & 63;
    const int shift = (r & 1) << 4;
    const unsigned int* slab = &s.priv[r >> 1][0][0];
    unsigned int acc = 0;
    #pragma unroll
    for (int t = 0; t < 32; t++)
        acc += (slab[bin * 32 + ((t + lane) & 31)] >> shift) & 0xFFFFu;

    out[((size_t)blockIdx.x * ROWS_PER_BLOCK + r) * NBINS + bin] =
        (float)acc * (1.0f / (float)ROW_LEN);
}

extern "C" void kernel_launch(void* const* d_in, const int* in_sizes, int n_in,
                              void* d_out, int out_size) {
    const float* x = (const float*)d_in[0];
    float* out = (float*)d_out;

    int nrows = in_sizes[0] / ROW_LEN;             // 4096
    int grid = nrows / ROWS_PER_BLOCK;             // 1024 blocks, single wave

    hist_rows_kernel<<<grid, BLOCK_THREADS>>>(x, out);
}

// round 11
// speedup vs baseline: 1.1503x; 1.1503x over previous
#include <cuda_runtime.h>

#define NBINS 64
#define ROW_LEN 8192
#define WARPS_PER_BLOCK 8          // 8 warps, ONE row per block
#define BLOCK_THREADS (WARPS_PER_BLOCK * 32)
#define WARP_ELEMS (ROW_LEN / WARPS_PER_BLOCK)   // 1024 elements per warp
#define VECS (WARP_ELEMS / 4 / 32)               // 8 float4 per lane

// Small-quantum oversubscription: 4096 one-row blocks stream over 148 SMs
// (8 resident each, ~3.5 waves) so the CLC scheduler load-balances away the
// cross-CTA finish-time spread that a single co-resident wave cannot fix.
// Counters: ONE plain u32 slab [bin][lane] shared by all 8 warps.
//   word index stride over lane = 1 -> bank = lane: every warp-wide
//   atomicAdd is exactly 1 wavefront, zero conflicts; intra-warp same-word
//   collisions impossible (distinct lanes); cross-warp hits merged by the
//   atomic. Max count per word = 8192 << 2^32. No packing, incr = +1.
// smem 8 KB/block; 256 thr x 8 blocks = 2048 thr/SM (thread-limited occ).
__global__ __launch_bounds__(BLOCK_THREADS, 8)
void hist_rows_kernel(const float* __restrict__ x, float* __restrict__ out) {
    __shared__ unsigned int priv[NBINS][32];

    const int warp = threadIdx.x >> 5;
    const int lane = threadIdx.x & 31;
    const int row  = blockIdx.x;

    unsigned int* cell = &priv[0][0] + lane;   // bank = lane forever

    // Zero all counters (64*32 = 2048 words / 256 threads = 8 each).
    unsigned int* flat = &priv[0][0];
    #pragma unroll
    for (int i = 0; i < (NBINS * 32) / BLOCK_THREADS; i++)
        flat[threadIdx.x + i * BLOCK_THREADS] = 0u;
    __syncthreads();

    const float4* __restrict__ xr =
        (const float4*)(x + (size_t)row * ROW_LEN + (size_t)warp * WARP_ELEMS) + lane;

    const float scale = 64.0f / 6.0f;   // NBINS / (VMAX - VMIN), fp32-rounded like ref

    // Exactly the reference fp32 sequence per element: (x - VMIN), * scale,
    // floor (round toward -inf), clamp to [0, 63]; then one conflict-free atomic.
    #define PROC4(v)                                                          \
        do {                                                                  \
            float _f[4] = {(v).x, (v).y, (v).z, (v).w};                       \
            _Pragma("unroll")                                                 \
            for (int _j = 0; _j < 4; _j++) {                                  \
                int _b = __float2int_rd(__fmul_rn(__fadd_rn(_f[_j], 3.0f), scale)); \
                _b = max(0, min(NBINS - 1, _b));                              \
                atomicAdd(&cell[_b * 32], 1u);                                \
            }                                                                 \
        } while (0)

    // 8 float4 per lane: two batches of 4 in flight (evict-first streaming).
    #pragma unroll 1
    for (int it = 0; it < VECS; it += 4) {
        float4 v0 = __ldcs(&xr[(it + 0) * 32]);
        float4 v1 = __ldcs(&xr[(it + 1) * 32]);
        float4 v2 = __ldcs(&xr[(it + 2) * 32]);
        float4 v3 = __ldcs(&xr[(it + 3) * 32]);
        PROC4(v0);
        PROC4(v1);
        PROC4(v2);
        PROC4(v3);
    }
    #undef PROC4

    __syncthreads();

    // Reduce: threads 0..63 each own one bin; sum 32 lane-columns with a
    // rotated index so concurrent readers hit distinct banks.
    if (threadIdx.x < NBINS) {
        const int bin = threadIdx.x;
        unsigned int s = 0;
        #pragma unroll
        for (int t = 0; t < 32; t++)
            s += priv[bin][(t + bin) & 31];
        out[(size_t)row * NBINS + bin] = (float)s * (1.0f / (float)ROW_LEN);
    }
}

extern "C" void kernel_launch(void* const* d_in, const int* in_sizes, int n_in,
                              void* d_out, int out_size) {
    const float* x = (const float*)d_in[0];
    float* out = (float*)d_out;

    int nrows = in_sizes[0] / ROW_LEN;             // 4096
    hist_rows_kernel<<<nrows, BLOCK_THREADS>>>(x, out);   // 1 row per block
}

// round 12
// speedup vs baseline: 1.1620x; 1.0102x over previous
#include <cuda_runtime.h>

#define NBINS 64
#define ROW_LEN 8192
#define WARPS_PER_BLOCK 4          // 4 warps, one HALF-row per block
#define BLOCK_THREADS (WARPS_PER_BLOCK * 32)
#define BLK_ELEMS (ROW_LEN / 2)                  // 4096 elements per block
#define WARP_ELEMS (BLK_ELEMS / WARPS_PER_BLOCK) // 1024 per warp
#define VECS (WARP_ELEMS / 4 / 32)               // 8 float4 per lane

// Finer-quantum oversubscription: 8192 half-row blocks (~7 streamed waves
// over 148 SMs, 16 resident each) so CLC work-stealing shrinks the idle
// tail to roughly one half-row block's duration. Two blocks per row write
// disjoint output halves -- bins [0,32) from the block owning the first
// half? No: both halves contain all bins, so each block atomically adds its
// partial counts? Avoided entirely: each block handles a contiguous half
// row and owns NO unique bins. Instead, the two blocks of a row write to
// the SAME 64 output bins -> use global atomicAdd on the f32 output? That
// breaks determinism. Solution used here: out is written with plain adds
// by splitting rows so each block owns its own output slice is impossible;
// therefore each block adds its partial histogram with atomicAdd on
// global memory (f32 add of exact integers/8192: both orders yield the
// same value since the final sum n/8192 is exact in fp32 for n <= 8192 and
// each partial is exact -- fp32 addition of two exact dyadic rationals
// with small exponents is exact, hence deterministic regardless of order).
// d_out is poisoned, so blocks with (rowhalf == 0) initialize via plain
// store is racy; instead use a two-pass-free trick: atomicExch-free --
// we instead have half 0 store (its partial) and half 1 atomicAdd after a
// grid-wide guarantee is impossible. SAFE CHOICE: pack both partials in
// u32 via atomicAdd on a global scratch? Simpler: keep ROW ownership for
// output by letting the block with half==0 write nothing... 
// -- Resolution: each block computes counts for its half and does
// atomicAdd(&out[bin], partial/8192.f). Initialization handled by an
// initial lightweight memset kernel launch (graph-capturable).
__global__ void zero_out_kernel(float* __restrict__ out, int n) {
    int i = blockIdx.x * blockDim.x + threadIdx.x;
    if (i < n) out[i] = 0.0f;
}

__global__ __launch_bounds__(BLOCK_THREADS, 16)
void hist_rows_kernel(const float* __restrict__ x, float* __restrict__ out) {
    __shared__ unsigned int priv[NBINS][32];

    const int warp = threadIdx.x >> 5;
    const int lane = threadIdx.x & 31;
    const int row  = blockIdx.x >> 1;
    const int halfsel = blockIdx.x & 1;

    unsigned int* cell = &priv[0][0] + lane;   // bank = lane forever

    // Zero all counters (64*32 = 2048 words / 128 threads = 16 each).
    unsigned int* flat = &priv[0][0];
    #pragma unroll
    for (int i = 0; i < (NBINS * 32) / BLOCK_THREADS; i++)
        flat[threadIdx.x + i * BLOCK_THREADS] = 0u;
    __syncthreads();

    const float4* __restrict__ xr =
        (const float4*)(x + (size_t)row * ROW_LEN + (size_t)halfsel * BLK_ELEMS
                        + (size_t)warp * WARP_ELEMS) + lane;

    const float scale = 64.0f / 6.0f;   // NBINS / (VMAX - VMIN), fp32-rounded like ref

    // Exactly the reference fp32 sequence per element: (x - VMIN), * scale,
    // floor (round toward -inf), clamp to [0, 63]; one conflict-free atomic.
    #define PROC4(v)                                                          \
        do {                                                                  \
            float _f[4] = {(v).x, (v).y, (v).z, (v).w};                       \
            _Pragma("unroll")                                                 \
            for (int _j = 0; _j < 4; _j++) {                                  \
                int _b = __float2int_rd(__fmul_rn(__fadd_rn(_f[_j], 3.0f), scale)); \
                _b = max(0, min(NBINS - 1, _b));                              \
                atomicAdd(&cell[_b * 32], 1u);                                \
            }                                                                 \
        } while (0)

    // 8 float4 per lane: batches of 4 in flight (evict-first streaming).
    #pragma unroll 1
    for (int it = 0; it < VECS; it += 4) {
        float4 v0 = __ldcs(&xr[(it + 0) * 32]);
        float4 v1 = __ldcs(&xr[(it + 1) * 32]);
        float4 v2 = __ldcs(&xr[(it + 2) * 32]);
        float4 v3 = __ldcs(&xr[(it + 3) * 32]);
        PROC4(v0);
        PROC4(v1);
        PROC4(v2);
        PROC4(v3);
    }
    #undef PROC4

    __syncthreads();

    // Reduce + publish partial. Each partial count/8192 is an exact fp32
    // dyadic rational (n*2^-13, n <= 4096) and the final per-bin total is
    // n_total*2^-13 with n_total <= 8192 -- exactly representable, so the
    // two-block fp32 atomicAdd is order-independent (deterministic).
    if (threadIdx.x < NBINS) {
        const int bin = threadIdx.x;
        unsigned int s = 0;
        #pragma unroll
        for (int t = 0; t < 32; t++)
            s += priv[bin][(t + bin) & 31];
        atomicAdd(&out[(size_t)row * NBINS + bin],
                  (float)s * (1.0f / (float)ROW_LEN));
    }
}

extern "C" void kernel_launch(void* const* d_in, const int* in_sizes, int n_in,
                              void* d_out, int out_size) {
    const float* x = (const float*)d_in[0];
    float* out = (float*)d_out;

    int nrows = in_sizes[0] / ROW_LEN;             // 4096

    // out is poisoned by the harness: zero it first (tiny: 256K floats).
    zero_out_kernel<<<(nrows * NBINS + 255) / 256, 256>>>(out, nrows * NBINS);

    hist_rows_kernel<<<nrows * 2, BLOCK_THREADS>>>(x, out);  // half-row blocks
}